// round 12
// baseline (speedup 1.0000x reference)
#include <cuda_runtime.h>
#include <cstdint>

#define BATCH  16
#define MAXLEN 128
#define NTOK   (BATCH * MAXLEN)   // 2048
#define VOCAB  32128
#define V4     (VOCAB / 4)        // 8032
#define EMB    768
#define NBLK   (NTOK / 2)         // 1024 blocks, 2 tokens each: ONE balanced wave

// ---------------------------------------------------------------------------
// Bit-exact replication of:
//   coord = jnp.linspace(-1, 1, size)[h]
//     JAX linspace (num>1): s = iota(f32 h)/f32(div); out = start*(1-s)+stop*s,
//     endpoint appended exactly as `stop`.
//   ix = ((coord + 1.0)*size - 1.0)/2.0 ;  round half-even ; clip [0, size-1]
// All ops forced to un-fused f32 (XLA emits separate rounded mul/add HLOs).
// ---------------------------------------------------------------------------
__device__ __forceinline__ int nearest_idx_rep(int h, int size) {
    float coord;
    if (h == size - 1) {
        coord = 1.0f;                                     // endpoint set to stop
    } else {
        float s = __fdiv_rn((float)h, (float)(size - 1)); // iota/div
        float t = __fsub_rn(1.0f, s);                     // (1 - step)
        float a = __fmul_rn(-1.0f, t);                    // start*(1-step)
        coord   = __fadd_rn(a, s);                        // + stop*step
    }
    float u1 = __fadd_rn(coord, 1.0f);
    float u2 = __fmul_rn(u1, (float)size);
    float u3 = __fsub_rn(u2, 1.0f);
    float ix = __fdiv_rn(u3, 2.0f);
    float r  = rintf(ix);                                 // round half-to-even
    r = fminf(fmaxf(r, 0.0f), (float)(size - 1));
    return (int)r;
}

// streaming argmax body for one token; '>' keeps first occurrence because
// per-thread indices strictly increase.
__device__ __forceinline__ void stream_argmax(
    const float4* __restrict__ L, const float4* __restrict__ G,
    int tid, float& best, int& bi)
{
    best = -3.402823466e38f;
    bi   = 0;
    #pragma unroll 4
    for (int i = tid; i < V4; i += 256) {
        float4 a = __ldcs(&L[i]);
        float4 c = __ldcs(&G[i]);
        float v0 = __fadd_rn(a.x, c.x);
        float v1 = __fadd_rn(a.y, c.y);
        float v2 = __fadd_rn(a.z, c.z);
        float v3 = __fadd_rn(a.w, c.w);
        int base = i << 2;
        if (v0 > best) { best = v0; bi = base;     }
        if (v1 > best) { best = v1; bi = base + 1; }
        if (v2 > best) { best = v2; bi = base + 2; }
        if (v3 > best) { best = v3; bi = base + 3; }
    }
}

// warp-level (maxval, min-index-on-tie) reduce == jnp.argmax semantics
__device__ __forceinline__ void warp_reduce_argmax(float& best, int& bi)
{
    #pragma unroll
    for (int o = 16; o > 0; o >>= 1) {
        float ov = __shfl_down_sync(0xffffffffu, best, o);
        int   oi = __shfl_down_sync(0xffffffffu, bi,   o);
        if (ov > best || (ov == best && oi < bi)) { best = ov; bi = oi; }
    }
}

// ---------------------------------------------------------------------------
// Single mega-kernel: 1024 blocks x 256 threads, 2 adjacent tokens per block
// (same batch), one perfectly-balanced wave at occ 8 (1024 <= 148*8).
//
// Phase 1: stream token0 argmax, warp-reduce, stash per-warp (no sync);
//          stream token1 argmax immediately (no bubble), warp-reduce, stash.
// Phase 2: per-batch passage bookkeeping (shared by both tokens):
//   psg_r    = roll(psg_ids, 1) with BOS=1
//   extr[k]  = (1 - mask[L-1-k]) * psg_r[k]
//   trunc[k] = extr[(k - sum(mask)) mod L]
//   flag[k]  = any_{i<=k} trunc[i] != 0  -> rb = flag[j] ? trunc[j] : -1
// Phase 3: ra = mask[j] ? nearest_idx(argmax) : -1 per token, dual gather:
//   out[tok,e] = (ra>=0 ? WE[ra,col(e)] : 0) + (rb>=0 ? WE[rb,col(e)] : 0)
// col(e) replicates _nearest_idx over linspace(-1,1,EMB) exactly (identity).
// ---------------------------------------------------------------------------
__global__ __launch_bounds__(256, 8) void k_all(
    const float4* __restrict__ lg, const float4* __restrict__ gm,
    const int* __restrict__ mask, const int* __restrict__ psg,
    const float* __restrict__ we, float* __restrict__ out)
{
    const int tok0 = blockIdx.x << 1;      // tokens tok0, tok0+1 (same batch)
    const int tid  = threadIdx.x;

    __shared__ int   s_mask[MAXLEN];
    __shared__ int   s_extr[MAXLEN];
    __shared__ int   s_red[4];
    __shared__ int   s_rb0, s_rb1, s_ra0, s_ra1;
    __shared__ float sv0[8], sv1[8];
    __shared__ int   si0[8], si1[8];

    const float4* L0 = lg + (size_t)tok0 * V4;
    const float4* G0 = gm + (size_t)tok0 * V4;

    float best; int bi;

    // ---- token 0 stream + warp reduce (sync-free stash) ----
    stream_argmax(L0, G0, tid, best, bi);
    warp_reduce_argmax(best, bi);
    if ((tid & 31) == 0) { sv0[tid >> 5] = best; si0[tid >> 5] = bi; }

    // ---- token 1 stream (launches immediately, hides reduce bubble) ----
    stream_argmax(L0 + V4, G0 + V4, tid, best, bi);

    // issue tiny L2-hot bookkeeping loads before the reduce
    const int b  = tok0 >> 7;              // batch
    const int j0 = tok0 & (MAXLEN - 1);    // position of token0 in batch
    int m = 0, pj = 0;
    if (tid < MAXLEN) {
        m  = __ldg(&mask[b * MAXLEN + tid]);
        pj = (tid == 0) ? 1 : __ldg(&psg[b * MAXLEN + tid - 1]);
    }

    warp_reduce_argmax(best, bi);
    if ((tid & 31) == 0) { sv1[tid >> 5] = best; si1[tid >> 5] = bi; }
    if (tid < MAXLEN) s_mask[tid] = m;
    __syncthreads();

    // ---- phase 2: shared passage bookkeeping ----
    if (tid < MAXLEN) {
        s_extr[tid] = (1 - s_mask[MAXLEN - 1 - tid]) * pj;
        unsigned wsum = __reduce_add_sync(0xffffffffu, (unsigned)m);
        if ((tid & 31) == 0) s_red[tid >> 5] = (int)wsum;
    }
    __syncthreads();

    if (tid < MAXLEN) {
        int shifts = s_red[0] + s_red[1] + s_red[2] + s_red[3];
        int pos    = (tid - shifts + MAXLEN) & (MAXLEN - 1);
        int tr     = s_extr[pos];
        if (tid == j0)     s_rb0 = tr;         // provisional: trunc[j0]
        if (tid == j0 + 1) s_rb1 = tr;         // provisional: trunc[j0+1]
        int key = (tr != 0) ? tid : MAXLEN;
        unsigned wmin = __reduce_min_sync(0xffffffffu, (unsigned)key);
        if ((tid & 31) == 0) s_red[tid >> 5] = (int)wmin;
    }
    __syncthreads();

    if (tid == 0) {
        int firstnz = min(min(s_red[0], s_red[1]), min(s_red[2], s_red[3]));
        if (j0     < firstnz) s_rb0 = -1;      // leading zeros -> no embed
        if (j0 + 1 < firstnz) s_rb1 = -1;

        // final block reduces for both tokens
        float b0 = sv0[0]; int i0 = si0[0];
        float b1 = sv1[0]; int i1 = si1[0];
        #pragma unroll
        for (int w = 1; w < 8; w++) {
            if (sv0[w] > b0 || (sv0[w] == b0 && si0[w] < i0)) { b0 = sv0[w]; i0 = si0[w]; }
            if (sv1[w] > b1 || (sv1[w] == b1 && si1[w] < i1)) { b1 = sv1[w]; i1 = si1[w]; }
        }
        s_ra0 = s_mask[j0]     ? nearest_idx_rep(i0, VOCAB) : -1;
        s_ra1 = s_mask[j0 + 1] ? nearest_idx_rep(i1, VOCAB) : -1;
    }
    __syncthreads();

    // ---- phase 3: dual gather + store for both tokens (coalesced) ----
    const int ra0 = s_ra0, rb0 = s_rb0;
    const int ra1 = s_ra1, rb1 = s_rb1;
    float* out0 = out + (size_t)tok0 * EMB;

    #pragma unroll
    for (int e = tid; e < EMB; e += 256) {
        int col = nearest_idx_rep(e, EMB);
        float v0 = 0.0f, v1 = 0.0f;
        if (ra0 >= 0) v0 = __ldg(&we[(size_t)ra0 * EMB + col]);
        if (rb0 >= 0) v0 = __fadd_rn(v0, __ldg(&we[(size_t)rb0 * EMB + col]));
        if (ra1 >= 0) v1 = __ldg(&we[(size_t)ra1 * EMB + col]);
        if (rb1 >= 0) v1 = __fadd_rn(v1, __ldg(&we[(size_t)rb1 * EMB + col]));
        out0[e]       = v0;
        out0[EMB + e] = v1;
    }
}

// ---------------------------------------------------------------------------
// Entry point. Inputs (metadata order):
//   0: logits           f32 [16,128,32128]
//   1: rwrt_attn_mask   i32 [16,128]
//   2: psg_input_ids    i32 [16,128]
//   3: word_embeddings  f32 [32128,768]
//   4: gumbel_noise     f32 [16,128,32128]
// Output: f32 [16,128,768]
// ---------------------------------------------------------------------------
extern "C" void kernel_launch(void* const* d_in, const int* in_sizes, int n_in,
                              void* d_out, int out_size)
{
    const float* logits = (const float*)d_in[0];
    const int*   mask   = (const int*)  d_in[1];
    const int*   psg    = (const int*)  d_in[2];
    const float* we     = (const float*)d_in[3];
    const float* gum    = (const float*)d_in[4];
    float*       out    = (float*)d_out;

    k_all<<<NBLK, 256>>>((const float4*)logits, (const float4*)gum,
                         mask, psg, we, out);
}